// round 5
// baseline (speedup 1.0000x reference)
#include <cuda_runtime.h>
#include <cuda_bf16.h>

// Soft "Until":
//   out[b,t,c] = (1/s) * log( sum_{k=0..kmax} 1/(E_k + exp(-s*psi[t+k])) )
//   E_0 = exp(-s),  E_k = sum_{j<k} exp(-s*phi[t+j]),  kmax = min(63, T-1-t)
//
// 2 adjacent outputs per thread; both channels packed into f32x2 (64-bit)
// arithmetic. Reciprocals merged pairwise: 1/a + 1/b = (a+b)*rcp(a*b).
// Pairing aligned to the parity-float4 shared layout so both outputs read the
// same float4 each iteration (no carries). k=0 term kept exact (E=exp(-s)).

#define THREADS 128
#define NT      256            // outputs (t positions) per block
#define W       64
#define NE      (NT + W)       // 320 window elements per block
#define NPAIR   (NE / 2)       // 160 parity pairs

typedef unsigned long long u64;

__device__ __forceinline__ float frcp(float x) {
    float r; asm("rcp.approx.f32 %0, %1;" : "=f"(r) : "f"(x)); return r;
}
__device__ __forceinline__ u64 padd(u64 a, u64 b) {
    u64 r; asm("add.rn.f32x2 %0, %1, %2;" : "=l"(r) : "l"(a), "l"(b)); return r;
}
__device__ __forceinline__ u64 pmul(u64 a, u64 b) {
    u64 r; asm("mul.rn.f32x2 %0, %1, %2;" : "=l"(r) : "l"(a), "l"(b)); return r;
}
__device__ __forceinline__ u64 pfma(u64 a, u64 b, u64 c) {
    u64 r; asm("fma.rn.f32x2 %0, %1, %2, %3;" : "=l"(r) : "l"(a), "l"(b), "l"(c)); return r;
}
__device__ __forceinline__ u64 pk(float lo, float hi) {
    u64 r; asm("mov.b64 %0, {%1, %2};" : "=l"(r) : "f"(lo), "f"(hi)); return r;
}
__device__ __forceinline__ float2 upk(u64 v) {
    float2 t; asm("mov.b64 {%0, %1}, %2;" : "=f"(t.x), "=f"(t.y) : "l"(v)); return t;
}
__device__ __forceinline__ u64 prcp(u64 v) {
    float2 t = upk(v); return pk(frcp(t.x), frcp(t.y));
}

__global__ void __launch_bounds__(THREADS) until_kernel(
    const float* __restrict__ phi,
    const float* __restrict__ psi,
    const void* __restrict__ scale_p,
    float* __restrict__ out,
    int T)
{
    // pair k holds elements 2k, 2k+1: (fx(2k), fy(2k), fx(2k+1), fy(2k+1))
    __shared__ float4 s_F[NPAIR];
    __shared__ float4 s_P[NPAIR];

    // scale dtype heuristic (int32/int64/float32, 1 element)
    int si = *(const int*)scale_p;
    float s = (si > 0 && si < (1 << 20)) ? (float)si : *(const float*)scale_p;
    const float ns = -s;

    const int b   = blockIdx.y;
    const int t0  = blockIdx.x * NT;       // even
    const int tid = threadIdx.x;

    const float4* phi4 = (const float4*)phi + (size_t)b * (T / 2);
    const float4* psi4 = (const float4*)psi + (size_t)b * (T / 2);

    for (int k = tid; k < NPAIR; k += THREADS) {
        int tp = t0 / 2 + k;
        float4 F = make_float4(0.f, 0.f, 0.f, 0.f);
        float4 P = make_float4(0.f, 0.f, 0.f, 0.f);
        if (2 * tp < T) {
            float4 ph = phi4[tp];
            float4 ps = psi4[tp];
            F.x = __expf(ns * ph.x); F.y = __expf(ns * ph.y);
            F.z = __expf(ns * ph.z); F.w = __expf(ns * ph.w);
            P.x = __expf(ns * ps.x); P.y = __expf(ns * ps.y);
            P.z = __expf(ns * ps.z); P.w = __expf(ns * ps.w);
        }
        s_F[k] = F;
        s_P[k] = P;
    }
    __syncthreads();

    const int tg = t0 + 2 * tid;           // global t of this thread's output 0
    if (tg >= T) return;

    const float E0    = __expf(ns);
    const float inv_s = frcp(s);
    float2* out2 = (float2*)out + (size_t)b * T;

    if (tg + 1 + W <= T) {
        // ---- fast path: both outputs have kmax = 63 ----
        const ulonglong2* Fp = (const ulonglong2*)s_F;
        const ulonglong2* Pp = (const ulonglong2*)s_P;

        ulonglong2 F0 = Fp[tid];
        ulonglong2 P0 = Pp[tid];
        const u64 E0v = pk(E0, E0);

        // out0: pair (k0, k1). k0 denom uses E0 (min_phi forced to 1).
        u64 dA = padd(E0v, P0.x);
        u64 Ea = F0.x;
        u64 dB = padd(Ea, P0.y);
        Ea = padd(Ea, F0.y);
        u64 S0 = pmul(padd(dA, dB), prcp(pmul(dA, dB)));

        // out1: lone k0 term; E accumulator starts at f(i0+1).
        u64 S1 = prcp(padd(E0v, P0.y));
        u64 Eb = F0.y;

        #pragma unroll
        for (int r = 1; r < 32; ++r) {
            ulonglong2 F1 = Fp[tid + r];
            ulonglong2 P1 = Pp[tid + r];

            // out0 terms k = 2r, 2r+1
            u64 a0 = padd(Ea, P1.x); Ea = padd(Ea, F1.x);
            u64 b0 = padd(Ea, P1.y); Ea = padd(Ea, F1.y);
            S0 = pfma(padd(a0, b0), prcp(pmul(a0, b0)), S0);

            // out1 terms k = 2r-1, 2r
            u64 a1 = padd(Eb, P1.x); Eb = padd(Eb, F1.x);
            u64 b1 = padd(Eb, P1.y); Eb = padd(Eb, F1.y);
            S1 = pfma(padd(a1, b1), prcp(pmul(a1, b1)), S1);
        }
        // out1 tail term k = 63 (element i0+64 = even of pair tid+32)
        {
            ulonglong2 P32 = Pp[tid + 32];
            S1 = padd(S1, prcp(padd(Eb, P32.x)));
        }

        float2 s0 = upk(S0), s1 = upk(S1);
        out2[tg]     = make_float2(__logf(s0.x) * inv_s, __logf(s0.y) * inv_s);
        out2[tg + 1] = make_float2(__logf(s1.x) * inv_s, __logf(s1.y) * inv_s);
    } else {
        // ---- slow path: windows truncated by T (last few outputs only) ----
        const float* sF = (const float*)s_F;
        const float* sP = (const float*)s_P;
        for (int o = 0; o < 2; ++o) {
            int t = tg + o;
            if (t >= T) break;
            int i = 2 * tid + o;           // local element index
            int kmax = min(W - 1, T - 1 - t);
            int base0 = (i >> 1) * 4 + (i & 1) * 2;
            float Sx = frcp(E0 + sP[base0]);
            float Sy = frcp(E0 + sP[base0 + 1]);
            float Ex = sF[base0], Ey = sF[base0 + 1];
            for (int k = 1; k <= kmax; ++k) {
                int e = i + k;
                int base = (e >> 1) * 4 + (e & 1) * 2;
                Sx += frcp(Ex + sP[base]);
                Sy += frcp(Ey + sP[base + 1]);
                Ex += sF[base]; Ey += sF[base + 1];
            }
            out2[t] = make_float2(__logf(Sx) * inv_s, __logf(Sy) * inv_s);
        }
    }
}

extern "C" void kernel_launch(void* const* d_in, const int* in_sizes, int n_in,
                              void* d_out, int out_size) {
    const float* phi   = (const float*)d_in[0];
    const float* psi   = (const float*)d_in[1];
    const void*  scale = d_in[2];
    float* out = (float*)d_out;

    const int T = 2048;
    const int B = out_size / (T * 2);     // out is [B, T, 2] float32

    dim3 grid((T + NT - 1) / NT, B);
    until_kernel<<<grid, THREADS>>>(phi, psi, scale, out, T);
}

// round 6
// speedup vs baseline: 1.1364x; 1.1364x over previous
#include <cuda_runtime.h>
#include <cuda_bf16.h>

// Soft "Until":
//   out[b,t,c] = (1/s) * log( sum_{k=0..kmax} 1/(E_k + exp(-s*psi[t+k])) )
//   E_0 = exp(-s),  E_k = sum_{j<k} exp(-s*phi[t+j]),  kmax = min(63, T-1-t)
//
// Split-k x2: thread (oPair, h) handles outputs (tg, tg+1), window half h.
//   h=0: out0 k=0..31, out1 k'=0..30
//   h=1: out0 k=32..63, out1 k'=31..63 (prefix rebuilt as forward positive sums)
// Partials combined via shfl_down(1). Pairwise rcp merge: 1/a+1/b=(a+b)*rcp(ab).
// Shared parity-packed float4 pairs -> all fast-path LDS are aligned LDS.128.

#define THREADS 128
#define NT      128            // outputs per block (t positions)
#define W       64
#define NE      (NT + W)       // 192
#define NPAIR   (NE / 2)       // 96

__device__ __forceinline__ float frcp(float x) {
    float r; asm("rcp.approx.f32 %0, %1;" : "=f"(r) : "f"(x)); return r;
}
// (a+b)*rcp(a*b) accumulated into S
__device__ __forceinline__ void merge2(float& S, float d1, float d2) {
    S = fmaf(d1 + d2, frcp(d1 * d2), S);
}

__global__ void __launch_bounds__(THREADS, 4) until_kernel(
    const float* __restrict__ phi,
    const float* __restrict__ psi,
    const void* __restrict__ scale_p,
    float* __restrict__ out,
    int T)
{
    // pair k holds elements 2k,2k+1: (fx(2k), fy(2k), fx(2k+1), fy(2k+1))
    __shared__ float4 s_F[NPAIR];
    __shared__ float4 s_P[NPAIR];

    int si = *(const int*)scale_p;
    float s = (si > 0 && si < (1 << 20)) ? (float)si : *(const float*)scale_p;
    const float ns = -s;

    const int b   = blockIdx.y;
    const int t0  = blockIdx.x * NT;
    const int tid = threadIdx.x;

    const float4* phi4 = (const float4*)phi + (size_t)b * (T / 2);
    const float4* psi4 = (const float4*)psi + (size_t)b * (T / 2);

    if (tid < NPAIR) {
        int tp = t0 / 2 + tid;
        float4 F = make_float4(0.f, 0.f, 0.f, 0.f);
        float4 P = make_float4(0.f, 0.f, 0.f, 0.f);
        if (2 * tp < T) {
            float4 ph = phi4[tp];
            float4 ps = psi4[tp];
            F.x = __expf(ns * ph.x); F.y = __expf(ns * ph.y);
            F.z = __expf(ns * ph.z); F.w = __expf(ns * ph.w);
            P.x = __expf(ns * ps.x); P.y = __expf(ns * ps.y);
            P.z = __expf(ns * ps.z); P.w = __expf(ns * ps.w);
        }
        s_F[tid] = F;
        s_P[tid] = P;
    }
    __syncthreads();

    const int oPair = tid >> 1;            // 0..63
    const int h     = tid & 1;             // window half
    const int i0    = 2 * oPair;           // local element index of out0
    const int tg    = t0 + i0;             // global t of out0 (< T always)

    const float E0c   = __expf(ns);
    const float inv_s = frcp(s);

    float S0x = 0.f, S0y = 0.f, S1x = 0.f, S1y = 0.f;

    if (tg + 1 + W <= T) {
        // ================= fast path =================
        if (h == 0) {
            float4 F0 = s_F[oPair];
            float4 P0 = s_P[oPair];
            // out0: k=0 (E0 special), k=1
            float Eax = F0.x, Eay = F0.y;
            {
                float d1x = E0c + P0.x, d2x = Eax + P0.z;
                float d1y = E0c + P0.y, d2y = Eay + P0.w;
                merge2(S0x, d1x, d2x);
                merge2(S0y, d1y, d2y);
                Eax += F0.z; Eay += F0.w;
            }
            // out1: lone k'=0
            S1x = frcp(E0c + P0.z);
            S1y = frcp(E0c + P0.w);
            float Ebx = F0.z, Eby = F0.w;

            #pragma unroll
            for (int r = 1; r < 16; ++r) {
                float4 F1 = s_F[oPair + r];
                float4 P1 = s_P[oPair + r];
                // out0: k = 2r, 2r+1
                float a0x = Eax + P1.x; Eax += F1.x;
                float b0x = Eax + P1.z; Eax += F1.z;
                merge2(S0x, a0x, b0x);
                float a0y = Eay + P1.y; Eay += F1.y;
                float b0y = Eay + P1.w; Eay += F1.w;
                merge2(S0y, a0y, b0y);
                // out1: k' = 2r-1, 2r
                float a1x = Ebx + P1.x; Ebx += F1.x;
                float b1x = Ebx + P1.z; Ebx += F1.z;
                merge2(S1x, a1x, b1x);
                float a1y = Eby + P1.y; Eby += F1.y;
                float b1y = Eby + P1.w; Eby += F1.w;
                merge2(S1y, a1y, b1y);
            }
        } else {
            // -------- prefix: Ea = sum f[e0..e31], C = sum f[e1..e31] --------
            float4 Fz = s_F[oPair];
            float aex = 0.f, aey = 0.f;    // evens e2..e30
            float aox = Fz.z, aoy = Fz.w;  // odds  e1..e31
            #pragma unroll
            for (int r = 1; r < 16; ++r) {
                float4 F = s_F[oPair + r];
                aex += F.x; aox += F.z;
                aey += F.y; aoy += F.w;
            }
            float Cx = aex + aox,      Cy = aey + aoy;
            float Eax = Fz.x + Cx,     Eay = Fz.y + Cy;
            float Ebx, Eby, fcx, fcy, pcx, pcy;
            {   // r = 16: out0 pair (32,33); out1 lone k'=31
                float4 F1 = s_F[oPair + 16];
                float4 P1 = s_P[oPair + 16];
                float a0x = Eax + P1.x; Eax += F1.x;
                float b0x = Eax + P1.z; Eax += F1.z;
                merge2(S0x, a0x, b0x);
                float a0y = Eay + P1.y; Eay += F1.y;
                float b0y = Eay + P1.w; Eay += F1.w;
                merge2(S0y, a0y, b0y);
                S1x = frcp(Cx + P1.x);
                S1y = frcp(Cy + P1.y);
                Ebx = Cx + F1.x; Eby = Cy + F1.y;
                fcx = F1.z; fcy = F1.w; pcx = P1.z; pcy = P1.w;
            }
            #pragma unroll
            for (int r = 17; r < 32; ++r) {
                float4 F1 = s_F[oPair + r];
                float4 P1 = s_P[oPair + r];
                // out0: k = 2r, 2r+1
                float a0x = Eax + P1.x; Eax += F1.x;
                float b0x = Eax + P1.z; Eax += F1.z;
                merge2(S0x, a0x, b0x);
                float a0y = Eay + P1.y; Eay += F1.y;
                float b0y = Eay + P1.w; Eay += F1.w;
                merge2(S0y, a0y, b0y);
                // out1: k' = 2r-2, 2r-1 (carry = odd of pair r-1)
                float a1x = Ebx + pcx; Ebx += fcx;
                float b1x = Ebx + P1.x; Ebx += F1.x;
                merge2(S1x, a1x, b1x);
                float a1y = Eby + pcy; Eby += fcy;
                float b1y = Eby + P1.y; Eby += F1.y;
                merge2(S1y, a1y, b1y);
                fcx = F1.z; fcy = F1.w; pcx = P1.z; pcy = P1.w;
            }
            {   // tail: out1 pair (62,63) uses carry(P31.z) + pair32 even
                float4 F2 = s_F[oPair + 32];
                float4 P2 = s_P[oPair + 32];
                float a1x = Ebx + pcx; Ebx += fcx;
                float b1x = Ebx + P2.x;
                merge2(S1x, a1x, b1x);
                float a1y = Eby + pcy; Eby += fcy;
                float b1y = Eby + P2.y;
                merge2(S1y, a1y, b1y);
            }
        }
    } else {
        // ================= slow path (tail of each batch row) =================
        const float* sF = (const float*)s_F;
        const float* sP = (const float*)s_P;
        #define ELEM(arr, i, c) arr[((i) >> 1) * 4 + ((i) & 1) * 2 + (c)]
        int kmaxa = T - 1 - tg;                 // >= 0
        int kmaxb = T - 2 - tg;                 // may be -1
        if (h == 0) {
            // out0: k = 0..min(31,kmaxa)
            S0x = frcp(E0c + ELEM(sP, i0, 0));
            S0y = frcp(E0c + ELEM(sP, i0, 1));
            float Ex = ELEM(sF, i0, 0), Ey = ELEM(sF, i0, 1);
            int ka = min(31, kmaxa);
            for (int k = 1; k <= ka; ++k) {
                S0x += frcp(Ex + ELEM(sP, i0 + k, 0));
                S0y += frcp(Ey + ELEM(sP, i0 + k, 1));
                Ex += ELEM(sF, i0 + k, 0); Ey += ELEM(sF, i0 + k, 1);
            }
            // out1: k' = 0..min(30,kmaxb)
            if (kmaxb >= 0) {
                int i1 = i0 + 1;
                S1x = frcp(E0c + ELEM(sP, i1, 0));
                S1y = frcp(E0c + ELEM(sP, i1, 1));
                float Fx = ELEM(sF, i1, 0), Fy = ELEM(sF, i1, 1);
                int kb = min(30, kmaxb);
                for (int k = 1; k <= kb; ++k) {
                    S1x += frcp(Fx + ELEM(sP, i1 + k, 0));
                    S1y += frcp(Fy + ELEM(sP, i1 + k, 1));
                    Fx += ELEM(sF, i1 + k, 0); Fy += ELEM(sF, i1 + k, 1);
                }
            }
        } else {
            // prefix: Ea = sum f[i0..i0+31], C = sum f[i0+1..i0+31]
            float Cx = 0.f, Cy = 0.f;
            for (int j = 1; j < 32; ++j) {
                Cx += ELEM(sF, i0 + j, 0);
                Cy += ELEM(sF, i0 + j, 1);
            }
            float Eax = ELEM(sF, i0, 0) + Cx;
            float Eay = ELEM(sF, i0, 1) + Cy;
            for (int k = 32; k <= kmaxa; ++k) {
                S0x += frcp(Eax + ELEM(sP, i0 + k, 0));
                S0y += frcp(Eay + ELEM(sP, i0 + k, 1));
                Eax += ELEM(sF, i0 + k, 0); Eay += ELEM(sF, i0 + k, 1);
            }
            if (kmaxb >= 31) {
                int i1 = i0 + 1;
                float Ebx = Cx, Eby = Cy;
                for (int k = 31; k <= kmaxb; ++k) {
                    S1x += frcp(Ebx + ELEM(sP, i1 + k, 0));
                    S1y += frcp(Eby + ELEM(sP, i1 + k, 1));
                    Ebx += ELEM(sF, i1 + k, 0); Eby += ELEM(sF, i1 + k, 1);
                }
            }
        }
        #undef ELEM
    }

    // ---- combine halves: partner lanes are (even, odd) adjacent ----
    S0x += __shfl_down_sync(0xffffffffu, S0x, 1);
    S0y += __shfl_down_sync(0xffffffffu, S0y, 1);
    S1x += __shfl_down_sync(0xffffffffu, S1x, 1);
    S1y += __shfl_down_sync(0xffffffffu, S1y, 1);

    if (h == 0) {
        float2* out2 = (float2*)out + (size_t)b * T;
        out2[tg] = make_float2(__logf(S0x) * inv_s, __logf(S0y) * inv_s);
        if (tg + 1 < T)
            out2[tg + 1] = make_float2(__logf(S1x) * inv_s, __logf(S1y) * inv_s);
    }
}

extern "C" void kernel_launch(void* const* d_in, const int* in_sizes, int n_in,
                              void* d_out, int out_size) {
    const float* phi   = (const float*)d_in[0];
    const float* psi   = (const float*)d_in[1];
    const void*  scale = d_in[2];
    float* out = (float*)d_out;

    const int T = 2048;
    const int B = out_size / (T * 2);     // out is [B, T, 2] float32

    dim3 grid(T / NT, B);
    until_kernel<<<grid, THREADS>>>(phi, psi, scale, out, T);
}

// round 7
// speedup vs baseline: 1.5000x; 1.3200x over previous
#include <cuda_runtime.h>
#include <cuda_bf16.h>

// Soft "Until":
//   out[b,t,c] = (1/s) * log( sum_{k=0..kmax} 1/(E_k + exp(-s*psi[t+k])) )
//   E_0 = exp(-s),  E_k = sum_{j<k} exp(-s*phi[t+j]),  kmax = min(63, T-1-t)
//
// 2 adjacent outputs per thread, scalar fp32, pairwise rcp merge
// (1/a + 1/b = (a+b)*rcp(a*b); products stay in [1e-32, 5e33] -> safe).
// Aligned pairing: out0 merges (k=2r,2r+1), out1 lone k'=0 then (2r-1,2r),
// so both outputs consume the SAME shared float4 each iteration.
// Explicit double-buffer prefetch of the shared float4s; generous reg budget
// via __launch_bounds__(128, 6) so ptxas can pipeline (R2's 32-reg clamp was
// the latency bottleneck).

#define THREADS 128
#define NT      256            // outputs (t positions) per block
#define W       64
#define NE      (NT + W)       // 320 window elements per block
#define NPAIR   (NE / 2)       // 160 parity pairs

__device__ __forceinline__ float frcp(float x) {
    float r; asm("rcp.approx.f32 %0, %1;" : "=f"(r) : "f"(x)); return r;
}
// S += 1/d1 + 1/d2 = (d1+d2) * rcp(d1*d2)
__device__ __forceinline__ void merge2(float& S, float d1, float d2) {
    S = fmaf(d1 + d2, frcp(d1 * d2), S);
}

__global__ void __launch_bounds__(THREADS, 6) until_kernel(
    const float* __restrict__ phi,
    const float* __restrict__ psi,
    const void* __restrict__ scale_p,
    float* __restrict__ out,
    int T)
{
    // pair k holds elements 2k,2k+1: (fx(2k), fy(2k), fx(2k+1), fy(2k+1))
    __shared__ float4 s_F[NPAIR];
    __shared__ float4 s_P[NPAIR];

    // scale dtype heuristic (int32/int64/float32, 1 element)
    int si = *(const int*)scale_p;
    float s = (si > 0 && si < (1 << 20)) ? (float)si : *(const float*)scale_p;
    const float ns = -s;

    const int b   = blockIdx.y;
    const int t0  = blockIdx.x * NT;       // even
    const int tid = threadIdx.x;

    const float4* phi4 = (const float4*)phi + (size_t)b * (T / 2);
    const float4* psi4 = (const float4*)psi + (size_t)b * (T / 2);

    #pragma unroll
    for (int k = tid; k < NPAIR; k += THREADS) {
        int tp = t0 / 2 + k;
        float4 F = make_float4(0.f, 0.f, 0.f, 0.f);
        float4 P = make_float4(0.f, 0.f, 0.f, 0.f);
        if (2 * tp < T) {
            float4 ph = phi4[tp];
            float4 ps = psi4[tp];
            F.x = __expf(ns * ph.x); F.y = __expf(ns * ph.y);
            F.z = __expf(ns * ph.z); F.w = __expf(ns * ph.w);
            P.x = __expf(ns * ps.x); P.y = __expf(ns * ps.y);
            P.z = __expf(ns * ps.z); P.w = __expf(ns * ps.w);
        }
        s_F[k] = F;
        s_P[k] = P;
    }
    __syncthreads();

    const int tg = t0 + 2 * tid;           // global t of this thread's output 0
    if (tg >= T) return;

    const float E0c   = __expf(ns);
    const float inv_s = frcp(s);
    float2* out2 = (float2*)out + (size_t)b * T;

    if (tg + 1 + W <= T) {
        // ================= fast path: both outputs have kmax = 63 ==========
        float4 F0 = s_F[tid];
        float4 P0 = s_P[tid];

        // out0: k=0 (E0 special) merged with k=1 (denom = f(i0) + p(i0+1))
        float S0x = 0.f, S0y = 0.f;
        merge2(S0x, E0c + P0.x, F0.x + P0.z);
        merge2(S0y, E0c + P0.y, F0.y + P0.w);
        float Eax = F0.x + F0.z;
        float Eay = F0.y + F0.w;

        // out1: lone k'=0
        float S1x = frcp(E0c + P0.z);
        float S1y = frcp(E0c + P0.w);
        float Ebx = F0.z;
        float Eby = F0.w;

        // prefetch r = 1
        float4 Fc = s_F[tid + 1];
        float4 Pc = s_P[tid + 1];

        #pragma unroll
        for (int r = 1; r < 32; ++r) {
            // prefetch r+1 (r=31 prefetches pair tid+32, used in the tail)
            float4 Fn = s_F[tid + r + 1];
            float4 Pn = s_P[tid + r + 1];

            // out0: k = 2r, 2r+1
            float a0x = Eax + Pc.x; Eax += Fc.x;
            float b0x = Eax + Pc.z; Eax += Fc.z;
            merge2(S0x, a0x, b0x);
            float a0y = Eay + Pc.y; Eay += Fc.y;
            float b0y = Eay + Pc.w; Eay += Fc.w;
            merge2(S0y, a0y, b0y);

            // out1: k' = 2r-1, 2r
            float a1x = Ebx + Pc.x; Ebx += Fc.x;
            float b1x = Ebx + Pc.z; Ebx += Fc.z;
            merge2(S1x, a1x, b1x);
            float a1y = Eby + Pc.y; Eby += Fc.y;
            float b1y = Eby + Pc.w; Eby += Fc.w;
            merge2(S1y, a1y, b1y);

            Fc = Fn; Pc = Pn;
        }
        // out1 tail: k' = 63, element i0+64 = even of pair tid+32 (in Pc now)
        S1x += frcp(Ebx + Pc.x);
        S1y += frcp(Eby + Pc.y);

        // both outputs contiguous & 16B-aligned: one STG.128
        float4 res;
        res.x = __logf(S0x) * inv_s;
        res.y = __logf(S0y) * inv_s;
        res.z = __logf(S1x) * inv_s;
        res.w = __logf(S1y) * inv_s;
        *(float4*)(out2 + tg) = res;
    } else {
        // ================= slow path: windows truncated by T ===============
        const float* sF = (const float*)s_F;
        const float* sP = (const float*)s_P;
        #define ELEM(arr, i, c) arr[((i) >> 1) * 4 + ((i) & 1) * 2 + (c)]
        for (int o = 0; o < 2; ++o) {
            int t = tg + o;
            if (t >= T) break;
            int i = 2 * tid + o;           // local element index
            int kmax = min(W - 1, T - 1 - t);
            float Sx = frcp(E0c + ELEM(sP, i, 0));
            float Sy = frcp(E0c + ELEM(sP, i, 1));
            float Ex = ELEM(sF, i, 0), Ey = ELEM(sF, i, 1);
            for (int k = 1; k <= kmax; ++k) {
                int e = i + k;
                Sx += frcp(Ex + ELEM(sP, e, 0));
                Sy += frcp(Ey + ELEM(sP, e, 1));
                Ex += ELEM(sF, e, 0); Ey += ELEM(sF, e, 1);
            }
            out2[t] = make_float2(__logf(Sx) * inv_s, __logf(Sy) * inv_s);
        }
        #undef ELEM
    }
}

extern "C" void kernel_launch(void* const* d_in, const int* in_sizes, int n_in,
                              void* d_out, int out_size) {
    const float* phi   = (const float*)d_in[0];
    const float* psi   = (const float*)d_in[1];
    const void*  scale = d_in[2];
    float* out = (float*)d_out;

    const int T = 2048;
    const int B = out_size / (T * 2);     // out is [B, T, 2] float32

    dim3 grid((T + NT - 1) / NT, B);
    until_kernel<<<grid, THREADS>>>(phi, psi, scale, out, T);
}

// round 11
// speedup vs baseline: 1.7493x; 1.1662x over previous
#include <cuda_runtime.h>
#include <cuda_bf16.h>

// Soft "Until":
//   out[b,t,c] = (1/s) * log( sum_{k=0..kmax} 1/(E_k + exp(-s*psi[t+k])) )
//   E_0 = exp(-s),  E_k = sum_{j<k} exp(-s*phi[t+j]),  kmax = min(63, T-1-t)
//
// 2 adjacent outputs per thread, scalar fp32, pairwise rcp merge
// (1/a + 1/b = (a+b)*rcp(a*b)).
// NO slow path: windows truncated by T are handled by padding shared memory
// with f=0 (E unchanged) and p=PADP=1e17 (term contributes exactly 1e-17,
// numerically zero vs S, and PADP*d_real < FLT_MAX so merges can't NaN).
// Shared-E trick: E_out0 = E_out1 + f(i0), so only one E chain per channel;
// out0 denominators are out1's + a constant.

#define THREADS 128
#define NT      256            // outputs (t positions) per block
#define W       64
#define NE      (NT + W)       // 320 window elements per block
#define NPAIR   (NE / 2)       // 160 parity pairs
#define PADP    1e17f

__device__ __forceinline__ float frcp(float x) {
    float r; asm("rcp.approx.f32 %0, %1;" : "=f"(r) : "f"(x)); return r;
}
// S += 1/d1 + 1/d2 = (d1+d2) * rcp(d1*d2)
__device__ __forceinline__ void merge2(float& S, float d1, float d2) {
    S = fmaf(d1 + d2, frcp(d1 * d2), S);
}

__global__ void __launch_bounds__(THREADS, 6) until_kernel(
    const float* __restrict__ phi,
    const float* __restrict__ psi,
    const void* __restrict__ scale_p,
    float* __restrict__ out,
    int T)
{
    // pair k holds elements 2k,2k+1: (fx(2k), fy(2k), fx(2k+1), fy(2k+1))
    __shared__ float4 s_F[NPAIR];
    __shared__ float4 s_P[NPAIR];

    // scale dtype heuristic (int32/int64/float32, 1 element)
    int si = *(const int*)scale_p;
    float s = (si > 0 && si < (1 << 20)) ? (float)si : *(const float*)scale_p;
    const float ns = -s;

    const int b   = blockIdx.y;
    const int t0  = blockIdx.x * NT;       // even
    const int tid = threadIdx.x;

    const float4* phi4 = (const float4*)phi + (size_t)b * (T / 2);
    const float4* psi4 = (const float4*)psi + (size_t)b * (T / 2);

    #pragma unroll
    for (int k = tid; k < NPAIR; k += THREADS) {
        int tp = t0 / 2 + k;
        float4 F, P;
        if (2 * tp < T) {                  // T even: pair fully in-range
            float4 ph = phi4[tp];
            float4 ps = psi4[tp];
            F.x = __expf(ns * ph.x); F.y = __expf(ns * ph.y);
            F.z = __expf(ns * ph.z); F.w = __expf(ns * ph.w);
            P.x = __expf(ns * ps.x); P.y = __expf(ns * ps.y);
            P.z = __expf(ns * ps.z); P.w = __expf(ns * ps.w);
        } else {                           // padding: dead terms
            F = make_float4(0.f, 0.f, 0.f, 0.f);
            P = make_float4(PADP, PADP, PADP, PADP);
        }
        s_F[k] = F;
        s_P[k] = P;
    }
    __syncthreads();

    const int tg = t0 + 2 * tid;           // global t of output 0 (< T always)

    const float E0c   = __expf(ns);
    const float inv_s = frcp(s);

    float4 F0 = s_F[tid];
    float4 P0 = s_P[tid];

    const float cFx = F0.x;                // E_out0 - E_out1 (constant)
    const float cFy = F0.y;

    // out0: k=0 (E0 special) merged with k=1 (denom = f(i0) + p(i0+1))
    float S0x = 0.f, S0y = 0.f;
    merge2(S0x, E0c + P0.x, cFx + P0.z);
    merge2(S0y, E0c + P0.y, cFy + P0.w);

    // out1: lone k'=0; single E chain (out1's)
    float S1x = frcp(E0c + P0.z);
    float S1y = frcp(E0c + P0.w);
    float Ebx = F0.z;
    float Eby = F0.w;

    // prefetch r = 1
    float4 Fc = s_F[tid + 1];
    float4 Pc = s_P[tid + 1];

    #pragma unroll
    for (int r = 1; r < 32; ++r) {
        // prefetch r+1 (r=31 prefetches pair tid+32, used in the tail)
        float4 Fn = s_F[tid + r + 1];
        float4 Pn = s_P[tid + r + 1];

        // x channel: out1 terms k'=2r-1,2r ; out0 terms k=2r,2r+1 (= a1+cF)
        float a1x = Ebx + Pc.x;  float a0x = a1x + cFx;
        Ebx += Fc.x;
        float b1x = Ebx + Pc.z;  float b0x = b1x + cFx;
        Ebx += Fc.z;
        merge2(S1x, a1x, b1x);
        merge2(S0x, a0x, b0x);

        // y channel
        float a1y = Eby + Pc.y;  float a0y = a1y + cFy;
        Eby += Fc.y;
        float b1y = Eby + Pc.w;  float b0y = b1y + cFy;
        Eby += Fc.w;
        merge2(S1y, a1y, b1y);
        merge2(S0y, a0y, b0y);

        Fc = Fn; Pc = Pn;
    }
    // out1 tail: k' = 63, element i0+64 = even of pair tid+32 (in Pc now)
    S1x += frcp(Ebx + Pc.x);
    S1y += frcp(Eby + Pc.y);

    // both outputs contiguous & 16B-aligned: one STG.128
    float2* out2 = (float2*)out + (size_t)b * T;
    float4 res;
    res.x = __logf(S0x) * inv_s;
    res.y = __logf(S0y) * inv_s;
    res.z = __logf(S1x) * inv_s;
    res.w = __logf(S1y) * inv_s;
    *(float4*)(out2 + tg) = res;
}

extern "C" void kernel_launch(void* const* d_in, const int* in_sizes, int n_in,
                              void* d_out, int out_size) {
    const float* phi   = (const float*)d_in[0];
    const float* psi   = (const float*)d_in[1];
    const void*  scale = d_in[2];
    float* out = (float*)d_out;

    const int T = 2048;
    const int B = out_size / (T * 2);     // out is [B, T, 2] float32

    dim3 grid((T + NT - 1) / NT, B);
    until_kernel<<<grid, THREADS>>>(phi, psi, scale, out, T);
}

// round 13
// speedup vs baseline: 1.7910x; 1.0239x over previous
#include <cuda_runtime.h>
#include <cuda_bf16.h>

// Soft "Until":
//   out[b,t,c] = (1/s) * log( sum_{k=0..kmax} 1/(E_k + exp(-s*psi[t+k])) )
//   E_0 = exp(-s),  E_k = sum_{j<k} exp(-s*phi[t+j]),  kmax = min(63, T-1-t)
//
// Channel-split version: thread = (output pair (t,t+1), channel c in {x,y}).
// 2x the threads of R11 at identical per-term instruction count (3 fma/term).
// Pairwise rcp merge: 1/a + 1/b = (a+b)*rcp(a*b).
// Shared-E trick: E_out0 = E_out1 + f(i0) -> single E chain, out0 denoms are
// out1's + const. No slow path: T-truncated windows handled by padding with
// f=0 (E exact) and p=1e17 (term contributes 1e-17 ~ 0; products < FLT_MAX).
// Shared layout: planar float arrays fx/fy/px/py -> all loop reads LDS.64,
// lane-stride-1, conflict-free. Output staged through shared for STG.128.

#define THREADS 256
#define NT      256            // outputs (t positions) per block
#define W       64
#define NE      (NT + W)       // 320 window elements per block
#define NPO     (NT / 2)       // 128 output pairs per block
#define PADP    1e17f

__device__ __forceinline__ float frcp(float x) {
    float r; asm("rcp.approx.f32 %0, %1;" : "=f"(r) : "f"(x)); return r;
}
// S += 1/d1 + 1/d2 = (d1+d2) * rcp(d1*d2)
__device__ __forceinline__ void merge2(float& S, float d1, float d2) {
    S = fmaf(d1 + d2, frcp(d1 * d2), S);
}

__global__ void __launch_bounds__(THREADS, 4) until_kernel(
    const float* __restrict__ phi,
    const float* __restrict__ psi,
    const void* __restrict__ scale_p,
    float* __restrict__ out,
    int T)
{
    // planar per-channel arrays; stage area reuses the front of this block
    __shared__ float sh[4 * NE];           // fx | fy | px | py
    float* const sFx = sh;
    float* const sFy = sh + NE;
    float* const sPx = sh + 2 * NE;
    float* const sPy = sh + 3 * NE;

    // scale dtype heuristic (int32/int64/float32, 1 element)
    int si = *(const int*)scale_p;
    float s = (si > 0 && si < (1 << 20)) ? (float)si : *(const float*)scale_p;
    const float ns = -s;

    const int b   = blockIdx.y;
    const int t0  = blockIdx.x * NT;       // even
    const int tid = threadIdx.x;

    const float2* phi2 = (const float2*)phi + (size_t)b * T;
    const float2* psi2 = (const float2*)psi + (size_t)b * T;

    #pragma unroll
    for (int i = tid; i < NE; i += THREADS) {
        int t = t0 + i;
        float fx, fy, px, py;
        if (t < T) {
            float2 ph = phi2[t];
            float2 ps = psi2[t];
            fx = __expf(ns * ph.x); fy = __expf(ns * ph.y);
            px = __expf(ns * ps.x); py = __expf(ns * ps.y);
        } else {                           // padding: dead terms
            fx = 0.f; fy = 0.f; px = PADP; py = PADP;
        }
        sFx[i] = fx; sFy[i] = fy;
        sPx[i] = px; sPy[i] = py;
    }
    __syncthreads();

    const int ch = tid >> 7;               // 0 = x (threads 0-127), 1 = y
    const int op = tid & 127;              // output-pair index
    const int i0 = 2 * op;                 // local element index of out0

    const float* F = ch ? sFy : sFx;
    const float* P = ch ? sPy : sPx;
    const float2* F2 = (const float2*)F;   // pair view (8B-aligned)
    const float2* P2 = (const float2*)P;

    const float E0c   = __expf(ns);
    const float inv_s = frcp(s);

    float2 F0 = F2[op];
    float2 P0 = P2[op];

    const float cF = F0.x;                 // E_out0 - E_out1 (constant)

    // out0: k=0 (E0 special) merged with k=1 (denom = f(i0) + p(i0+1))
    float S0 = 0.f;
    merge2(S0, E0c + P0.x, cF + P0.y);

    // out1: lone k'=0; single E chain (out1's)
    float S1 = frcp(E0c + P0.y);
    float Eb = F0.y;

    // prefetch r = 1
    float2 Fc = F2[op + 1];
    float2 Pc = P2[op + 1];

    #pragma unroll
    for (int r = 1; r < 32; ++r) {
        // prefetch r+1 (r=31 prefetches pair op+32, used in the tail)
        float2 Fn = F2[op + r + 1];
        float2 Pn = P2[op + r + 1];

        // out1 terms k'=2r-1,2r ; out0 terms k=2r,2r+1 (= out1's + cF)
        float a1 = Eb + Pc.x;  float a0 = a1 + cF;
        Eb += Fc.x;
        float b1 = Eb + Pc.y;  float b0 = b1 + cF;
        Eb += Fc.y;
        merge2(S1, a1, b1);
        merge2(S0, a0, b0);

        Fc = Fn; Pc = Pn;
    }
    // out1 tail: k' = 63, element i0+64 = even of pair op+32 (in Pc now)
    S1 += frcp(Eb + Pc.x);

    float r0 = __logf(S0) * inv_s;
    float r1 = __logf(S1) * inv_s;

    // ---- stage through shared for coalesced STG.128 ----
    __syncthreads();                       // all loop reads done
    float2* stg = (float2*)sh;             // stage[ch*128 + op] = (r0, r1)
    stg[ch * 128 + op] = make_float2(r0, r1);
    __syncthreads();

    if (tid < NPO) {
        float2 vx = stg[tid];              // (x(t=2j), x(t=2j+1))
        float2 vy = stg[128 + tid];        // (y(t=2j), y(t=2j+1))
        float2* out2 = (float2*)out + (size_t)b * T;
        float4 res = make_float4(vx.x, vy.x, vx.y, vy.y);
        *(float4*)(out2 + t0 + 2 * tid) = res;
    }
}

extern "C" void kernel_launch(void* const* d_in, const int* in_sizes, int n_in,
                              void* d_out, int out_size) {
    const float* phi   = (const float*)d_in[0];
    const float* psi   = (const float*)d_in[1];
    const void*  scale = d_in[2];
    float* out = (float*)d_out;

    const int T = 2048;
    const int B = out_size / (T * 2);     // out is [B, T, 2] float32

    dim3 grid((T + NT - 1) / NT, B);
    until_kernel<<<grid, THREADS>>>(phi, psi, scale, out, T);
}

// round 15
// speedup vs baseline: 2.2222x; 1.2407x over previous
#include <cuda_runtime.h>
#include <cuda_bf16.h>

// Soft "Until":
//   out[b,t,c] = (1/s) * log( sum_{k=0..kmax} 1/(E_k + exp(-s*psi[t+k])) )
//   E_0 = exp(-s),  E_k = sum_{j<k} exp(-s*phi[t+j]),  kmax = min(63, T-1-t)
//
// Thread = (output pair (t,t+1), channel). NT=128 -> 1024 blocks (6.9/SM,
// ~1% wave imbalance vs 16% at 512). Preamble precomputes per parity-pair:
//   stream = (pe, h=fe+po, g=fe+fo, po)  -> loop does ONE LDS.128 / iter
//   raw    = (fe, fo)                    -> boundary terms only
// Loop per iter (4 terms): a1=Eb+pe, b1=Eb+h, u=a1+b1, v=a1*b1,
//   S1 += u*rcp(v);  out0 via shared-E const cF=fe(i0):
//   w=u+cF, prod0=fma(cF,w,v), sum0=w+cF, S0 += sum0*rcp(prod0);  Eb+=g.
// = 10 fma + 2 MUFU + 1 LDS.128. No slow path: pad f=0, p=1e17 (dead terms).

#define THREADS 128
#define NT      128            // outputs (t positions) per block
#define W       64
#define NE      (NT + W)       // 192
#define NPAIR   (NE / 2)       // 96
#define NPO     (NT / 2)       // 64 output pairs
#define PADP    1e17f

__device__ __forceinline__ float frcp(float x) {
    float r; asm("rcp.approx.f32 %0, %1;" : "=f"(r) : "f"(x)); return r;
}
__device__ __forceinline__ void merge2(float& S, float d1, float d2) {
    S = fmaf(d1 + d2, frcp(d1 * d2), S);
}

__global__ void __launch_bounds__(THREADS, 6) until_kernel(
    const float* __restrict__ phi,
    const float* __restrict__ psi,
    const void* __restrict__ scale_p,
    float* __restrict__ out,
    int T)
{
    __shared__ float4 s_stream[2][NPAIR];  // (pe, h, g, po) per channel
    __shared__ float2 s_raw[2][NPAIR];     // (fe, fo)
    __shared__ float2 s_stage[2][NPO];     // (out0, out1) per channel

    // scale dtype heuristic (int32/int64/float32, 1 element)
    int si = *(const int*)scale_p;
    float s = (si > 0 && si < (1 << 20)) ? (float)si : *(const float*)scale_p;
    const float ns = -s;

    const int b   = blockIdx.y;
    const int t0  = blockIdx.x * NT;       // even
    const int tid = threadIdx.x;

    const float4* phi4 = (const float4*)phi + (size_t)b * (T / 2);
    const float4* psi4 = (const float4*)psi + (size_t)b * (T / 2);

    // ---- preamble: one parity pair per thread (tid < NPAIR) ----
    if (tid < NPAIR) {
        int tp = t0 / 2 + tid;
        float fex, fox, pex, pox, fey, foy, pey, poy;
        if (2 * tp < T) {
            float4 ph = phi4[tp];          // (x(2k), y(2k), x(2k+1), y(2k+1))
            float4 ps = psi4[tp];
            fex = __expf(ns * ph.x); fey = __expf(ns * ph.y);
            fox = __expf(ns * ph.z); foy = __expf(ns * ph.w);
            pex = __expf(ns * ps.x); pey = __expf(ns * ps.y);
            pox = __expf(ns * ps.z); poy = __expf(ns * ps.w);
        } else {
            fex = fox = fey = foy = 0.f;
            pex = pox = pey = poy = PADP;
        }
        s_stream[0][tid] = make_float4(pex, fex + pox, fex + fox, pox);
        s_stream[1][tid] = make_float4(pey, fey + poy, fey + foy, poy);
        s_raw[0][tid] = make_float2(fex, fox);
        s_raw[1][tid] = make_float2(fey, foy);
    }
    __syncthreads();

    const int ch = tid >> 6;               // 0 = x, 1 = y
    const int op = tid & 63;               // output-pair index

    const float4* Q  = s_stream[ch];
    const float2  R0 = s_raw[ch][op];

    const float E0c   = __expf(ns);
    const float inv_s = frcp(s);

    float4 Q0 = Q[op];                     // (pe, h0, g0, po)
    const float cF = R0.x;                 // fe(i0) = E_out0 - E_out1
    const float c2 = cF + cF;

    // out0: k=0 (E0 special) merged with k=1; note cF + po == h0
    float S0 = 0.f;
    merge2(S0, E0c + Q0.x, Q0.y);
    // out1: lone k'=0
    float S1 = frcp(E0c + Q0.w);
    float Eb = R0.y;                       // fo(i0)

    float4 Qc = Q[op + 1];                 // prefetch r=1
    #pragma unroll
    for (int r = 1; r < 32; ++r) {
        float4 Qn = Q[op + r + 1];         // r=31 prefetches op+32 (tail)

        float a1 = Eb + Qc.x;              // out1 k'=2r-1
        float b1 = Eb + Qc.y;              // out1 k'=2r  (Eb + fe + po)
        float u  = a1 + b1;
        float v  = a1 * b1;
        S1 = fmaf(u, frcp(v), S1);

        float w  = u + cF;
        float p0 = fmaf(cF, w, v);         // (a1+cF)(b1+cF)
        float s0 = w + cF;                 // a0 + b0
        S0 = fmaf(s0, frcp(p0), S0);

        Eb += Qc.z;                        // += fe + fo
        Qc = Qn;
    }
    // out1 tail: k'=63 uses pe of pair op+32
    S1 += frcp(Eb + Qc.x);

    s_stage[ch][op] = make_float2(__logf(S0) * inv_s, __logf(S1) * inv_s);
    __syncthreads();

    if (tid < NPO) {
        float2 vx = s_stage[0][tid];
        float2 vy = s_stage[1][tid];
        float2* out2 = (float2*)out + (size_t)b * T;
        float4 res = make_float4(vx.x, vy.x, vx.y, vy.y);
        *(float4*)(out2 + t0 + 2 * tid) = res;
    }
}

extern "C" void kernel_launch(void* const* d_in, const int* in_sizes, int n_in,
                              void* d_out, int out_size) {
    const float* phi   = (const float*)d_in[0];
    const float* psi   = (const float*)d_in[1];
    const void*  scale = d_in[2];
    float* out = (float*)d_out;

    const int T = 2048;
    const int B = out_size / (T * 2);     // out is [B, T, 2] float32

    dim3 grid(T / NT, B);
    until_kernel<<<grid, THREADS>>>(phi, psi, scale, out, T);
}